// round 6
// baseline (speedup 1.0000x reference)
#include <cuda_runtime.h>
#include <stdint.h>

#define Bn 4096
#define Dn 16
#define Mn 4
#define Rn 2048
#define Cn 10
#define BT 32
#define WARPS 16
#define THREADS 512
#define HALF_R 1024
#define RPW 64          // rules per warp (HALF_R / WARPS)
#define EPSV 1e-9f

// scratch (module-load allocation, allowed)
__device__ uint4 g_offp[Rn];          // packed table byte-offsets
__device__ float g_cs[Rn * 12];       // folded consequents (+1.0, 0.0 pad)
__device__ float g_psum[2 * Bn];      // per-half rule-sum partials
__device__ float g_pacc[2 * Bn * Cn]; // per-half out partials
__device__ float g_ft[(size_t)Rn * Bn]; // raw f, transposed [r][b]

__device__ __forceinline__ void ffma2(unsigned long long& acc,
                                      unsigned long long a,
                                      unsigned long long b) {
    asm("fma.rn.f32x2 %0, %1, %2, %0;" : "+l"(acc) : "l"(a), "l"(b));
}
__device__ __forceinline__ unsigned long long bcast2(float f) {
    unsigned long long r;
    asm("mov.b64 %0, {%1, %1};" : "=l"(r) : "f"(f));
    return r;
}

// ---------------------------------------------------------------------------
// prep: high-MLP. thread-per-(r,c) consequent fold + thread-per-r offsets.
// 20480 fold threads + 2048 offset threads = 22528 = 88 blocks x 256.
// ---------------------------------------------------------------------------
__global__ void anfis_prep(const float* __restrict__ cons,
                           const int*   __restrict__ rules) {
    const int idx = blockIdx.x * 256 + threadIdx.x;
    if (idx < Rn * Cn) {
        const int r = idx / Cn, c = idx % Cn;
        const float* p = cons + (size_t)r * 170 + c;
        float a = 0.f;
#pragma unroll
        for (int j = 0; j < 17; j++) a += p[j * 10];   // 17 independent LDGs
        g_cs[(size_t)r * 12 + c] = a;
        if (c == 0) {
            g_cs[(size_t)r * 12 + 10] = 1.f;   // fsum accumulator slot
            g_cs[(size_t)r * 12 + 11] = 0.f;
        }
    } else if (idx < Rn * Cn + Rn) {
        const int r = idx - Rn * Cn;
        const int4* rp = (const int4*)(rules + (size_t)r * Dn);
        int4 q0 = rp[0], q1 = rp[1], q2 = rp[2], q3 = rp[3];
        int v[16] = {q0.x,q0.y,q0.z,q0.w, q1.x,q1.y,q1.z,q1.w,
                     q2.x,q2.y,q2.z,q2.w, q3.x,q3.y,q3.z,q3.w};
        uint32_t ix[5];
#pragma unroll
        for (int g = 0; g < 4; g++)
            ix[g] = ((uint32_t)v[3*g] & 3u) | (((uint32_t)v[3*g+1] & 3u) << 2)
                  | (((uint32_t)v[3*g+2] & 3u) << 4);
        ix[4] = ((uint32_t)v[12] & 3u) | (((uint32_t)v[13] & 3u) << 2)
              | (((uint32_t)v[14] & 3u) << 4) | (((uint32_t)v[15] & 3u) << 6);
        uint4 o;
        o.x = ( ix[0]         * 128u) | (((64u  + ix[1]) * 128u) << 16);
        o.y = ((128u + ix[2]) * 128u) | (((192u + ix[3]) * 128u) << 16);
        o.z = (256u + ix[4]) * 128u;
        o.w = 0;
        g_offp[r] = o;
    }
}

// ---------------------------------------------------------------------------
// main: 2 CTAs per batch tile (rule-split), 2 CTAs/SM, 512-entry table.
// writes raw f transposed to g_ft (coalesced, no smem staging).
// ---------------------------------------------------------------------------
// smem floats: tbl 512*32=16384 | mf 64*32=2048 | pair 32*32=1024
//              xs 512 | red 12*32=384
#define SMEM_FLOATS (16384 + 2048 + 1024 + 512 + 384)
#define SMEM_BYTES  (SMEM_FLOATS * 4)

__global__ void __launch_bounds__(THREADS, 2)
anfis_main(const float* __restrict__ x,
           const float* __restrict__ centers,
           const float* __restrict__ widths,
           int write_aux) {
    extern __shared__ float sm[];
    float* tbl  = sm;               // 512*32
    float* mf   = tbl + 16384;      // 64*32
    float* pair = mf + 2048;        // 32*32
    float* xs   = pair + 1024;      // 32*16
    float* red  = xs + 512;         // 12*32

    const int tid  = threadIdx.x;
    const int w    = tid >> 5;
    const int lane = tid & 31;
    const int tile = blockIdx.x >> 1;
    const int rank = blockIdx.x & 1;
    const int b0   = tile * BT;

    // ---- build phase ----
    for (int i = tid; i < BT * Dn; i += THREADS)
        xs[i] = x[(size_t)b0 * Dn + i];
    if (tid < 384) red[tid] = 0.f;
    __syncthreads();

    for (int e = tid; e < 64 * 32; e += THREADS) {
        int dm = e >> 5, b = e & 31;
        int d = dm >> 2, m = dm & 3;
        float cc = centers[d * Mn + m];
        float ww = widths[d * Mn + m];
        float df = xs[b * Dn + d] - cc;
        mf[dm * 32 + b] = expf(-df * df / (2.f * ww * ww));
    }
    __syncthreads();

    // groups 0-3 (3 dims each, 64 entries)
    for (int pp = w; pp < 256; pp += WARPS) {
        int g = pp >> 6, idx = pp & 63;
        tbl[pp * 32 + lane] =
            mf[((3*g + 0) * 4 + ( idx       & 3)) * 32 + lane] *
            mf[((3*g + 1) * 4 + ((idx >> 2) & 3)) * 32 + lane] *
            mf[((3*g + 2) * 4 + ( idx >> 4     )) * 32 + lane];
    }
    // pair tables for group 4
    for (int pp = w; pp < 32; pp += WARPS) {
        int grp = pp >> 4, i2 = pp & 15;
        int d0 = 12 + grp * 2;
        pair[pp * 32 + lane] =
            mf[(d0     * 4 + (i2 & 3))  * 32 + lane] *
            mf[((d0+1) * 4 + (i2 >> 2)) * 32 + lane];
    }
    __syncthreads();
    for (int pp = w; pp < 256; pp += WARPS) {
        tbl[(256 + pp) * 32 + lane] =
            pair[(pp & 15) * 32 + lane] * pair[(16 + (pp >> 4)) * 32 + lane];
    }
    __syncthreads();

    // ---- main loop: 64 rules/warp; raw f -> g_ft[r][b] (coalesced) ----
    const char* tb = (const char*)tbl + lane * 4;
    const ulonglong2* cs2 = (const ulonglong2*)g_cs;
    const int rbase = rank * HALF_R + w * RPW;

    unsigned long long a01 = 0, a23 = 0, a45 = 0, a67 = 0, a89 = 0, aSF = 0;

#pragma unroll 8
    for (int rl = 0; rl < RPW; rl++) {
        const int r = rbase + rl;
        const uint4 o = g_offp[r];
        float f0 = *(const float*)(tb + (o.x & 0xFFFFu));
        float f1 = *(const float*)(tb + (o.x >> 16));
        float f2 = *(const float*)(tb + (o.y & 0xFFFFu));
        float f3 = *(const float*)(tb + (o.y >> 16));
        float f4 = *(const float*)(tb + o.z);
        float f = ((f0 * f1) * (f2 * f3)) * f4;
        if (write_aux)
            g_ft[(size_t)r * Bn + b0 + lane] = f;
        unsigned long long fp = bcast2(f);
        ulonglong2 v0 = cs2[r * 3 + 0];
        ulonglong2 v1 = cs2[r * 3 + 1];
        ulonglong2 v2 = cs2[r * 3 + 2];
        ffma2(a01, fp, v0.x); ffma2(a23, fp, v0.y);
        ffma2(a45, fp, v1.x); ffma2(a67, fp, v1.y);
        ffma2(a89, fp, v2.x); ffma2(aSF, fp, v2.y);  // .lo accumulates fsum
    }

    // ---- CTA reduction ----
    {
        union { unsigned long long u; float2 f; } c0, c1, c2, c3, c4, c5;
        c0.u = a01; c1.u = a23; c2.u = a45; c3.u = a67; c4.u = a89; c5.u = aSF;
        atomicAdd(&red[ 0 * 32 + lane], c0.f.x);
        atomicAdd(&red[ 1 * 32 + lane], c0.f.y);
        atomicAdd(&red[ 2 * 32 + lane], c1.f.x);
        atomicAdd(&red[ 3 * 32 + lane], c1.f.y);
        atomicAdd(&red[ 4 * 32 + lane], c2.f.x);
        atomicAdd(&red[ 5 * 32 + lane], c2.f.y);
        atomicAdd(&red[ 6 * 32 + lane], c3.f.x);
        atomicAdd(&red[ 7 * 32 + lane], c3.f.y);
        atomicAdd(&red[ 8 * 32 + lane], c4.f.x);
        atomicAdd(&red[ 9 * 32 + lane], c4.f.y);
        atomicAdd(&red[10 * 32 + lane], c5.f.x);
    }
    __syncthreads();

    if (tid < 32)
        g_psum[rank * Bn + b0 + tid] = red[10 * 32 + tid];
    if (tid < 320) {
        int b = tid & 31, c = tid >> 5;
        g_pacc[(size_t)rank * Bn * Cn + (size_t)(b0 + b) * Cn + c] = red[c * 32 + b];
    }
}

// ---------------------------------------------------------------------------
// norm: 128 CTAs x 1024 thr. transpose+rescale g_ft -> nf, emit out + xext.
// ---------------------------------------------------------------------------
__global__ void __launch_bounds__(1024, 1)
anfis_norm(const float* __restrict__ x,
           float* __restrict__ out,
           float* __restrict__ nf,
           float* __restrict__ xext,
           int write_aux) {
    __shared__ float fsm[128 * 33];
    __shared__ float inv[32];
    __shared__ float sxs[32];

    const int t  = threadIdx.x;
    const int b0 = blockIdx.x * BT;
    const int w  = t >> 5;       // warp / row id
    const int l  = t & 31;

    if (t < 32) {
        inv[t] = 1.f / (g_psum[b0 + t] + g_psum[Bn + b0 + t] + EPSV);
        float s = 1.f;
#pragma unroll
        for (int d = 0; d < Dn; d++) s += x[(size_t)(b0 + t) * Dn + d];
        sxs[t] = s;
    }
    __syncthreads();

    if (write_aux) {
        for (int tile2 = 0; tile2 < Rn / 128; tile2++) {
            const int r0 = tile2 * 128;
            // load 128 rules x 32 rows (coalesced 128B per rule-row)
#pragma unroll
            for (int s = 0; s < 4; s++) {
                int i = w + 32 * s;
                fsm[i * 33 + l] = g_ft[(size_t)(r0 + i) * Bn + b0 + l];
            }
            __syncthreads();
            // write normalized, transposed (coalesced, conflict-free LDS)
            float iv = inv[w];
#pragma unroll
            for (int k = 0; k < 4; k++)
                nf[(size_t)(b0 + w) * Rn + r0 + l + 32 * k] =
                    fsm[(l + 32 * k) * 33 + w] * iv;
            __syncthreads();
        }
        if (t < BT * (Dn + 1)) {
            int b = t / (Dn + 1), j = t % (Dn + 1);
            xext[(size_t)(b0 + b) * (Dn + 1) + j] =
                (j < Dn) ? x[(size_t)(b0 + b) * Dn + j] : 1.f;
        }
    }

    if (t < BT * Cn) {
        int b = t & 31, c = t >> 5;
        float a = g_pacc[(size_t)(b0 + b) * Cn + c] +
                  g_pacc[(size_t)Bn * Cn + (size_t)(b0 + b) * Cn + c];
        out[(size_t)(b0 + b) * Cn + c] = sxs[b] * inv[b] * a;
    }
}

// ---------------------------------------------------------------------------
extern "C" void kernel_launch(void* const* d_in, const int* in_sizes, int n_in,
                              void* d_out, int out_size) {
    const float* x       = (const float*)d_in[0];
    const float* centers = (const float*)d_in[1];
    const float* widths  = (const float*)d_in[2];
    const float* cons    = (const float*)d_in[3];
    const int*   rules   = (const int*)d_in[4];

    float* out = (float*)d_out;
    const long total = (long)Bn * Cn + (long)Bn * Rn + (long)Bn * (Dn + 1);
    const int write_aux = (out_size >= total) ? 1 : 0;
    float* nf   = out + (size_t)Bn * Cn;
    float* xext = nf + (size_t)Bn * Rn;

    anfis_prep<<<(Rn * Cn + Rn + 255) / 256, 256>>>(cons, rules);

    cudaFuncSetAttribute(anfis_main, cudaFuncAttributeMaxDynamicSharedMemorySize,
                         SMEM_BYTES);
    anfis_main<<<(Bn / BT) * 2, THREADS, SMEM_BYTES>>>(x, centers, widths,
                                                       write_aux);

    anfis_norm<<<Bn / BT, 1024>>>(x, out, nf, xext, write_aux);
}

// round 8
// speedup vs baseline: 1.1302x; 1.1302x over previous
#include <cuda_runtime.h>
#include <stdint.h>

#define Bn 4096
#define Dn 16
#define Mn 4
#define Rn 2048
#define Cn 10
#define BT 32
#define WARPS 32
#define THREADS 1024
#define RPW 64          // rules per warp
#define CHUNK 16
#define SSTRIDE 34      // stage stride: conflict-free STS + transposed LDS
#define EPSV 1e-9f

// scratch (module-load allocation, allowed)
__device__ uint4 g_offp[Rn];          // 4 packed byte-offsets into tbl
__device__ float g_cs[Rn * 12];       // folded consequents (+1.0 fsum slot, 0 pad)

__device__ __forceinline__ void ffma2(unsigned long long& acc,
                                      unsigned long long a,
                                      unsigned long long b) {
    asm("fma.rn.f32x2 %0, %1, %2, %0;" : "+l"(acc) : "l"(a), "l"(b));
}
__device__ __forceinline__ unsigned long long bcast2(float f) {
    unsigned long long r;
    asm("mov.b64 %0, {%1, %1};" : "=l"(r) : "f"(f));
    return r;
}

// ---------------------------------------------------------------------------
// prep: 8 rules per 256-thread CTA, smem-staged (fast, ~1.5us)
// ---------------------------------------------------------------------------
__global__ void anfis_prep(const float* __restrict__ cons,
                           const int*   __restrict__ rules) {
    __shared__ float s[8 * 170];
    const int r0 = blockIdx.x * 8;
    const float* base = cons + (size_t)r0 * 170;
    for (int i = threadIdx.x; i < 8 * 170; i += 256) s[i] = base[i];
    __syncthreads();
    const int t = threadIdx.x;
    if (t < 80) {
        int rr = t / 10, c = t % 10;
        float a = 0.f;
#pragma unroll
        for (int j = 0; j < 17; j++) a += s[rr * 170 + j * 10 + c];
        g_cs[(size_t)(r0 + rr) * 12 + c] = a;
    } else if (t < 96) {
        int rr = (t - 80) >> 1;
        // slot [10] = 1.0 -> fsum accumulates in the FFMA2 stream; [11] = 0
        g_cs[(size_t)(r0 + rr) * 12 + 10 + ((t - 80) & 1)] =
            ((t - 80) & 1) ? 0.f : 1.f;
    } else if (t < 104) {
        int rr = t - 96;
        const int* rp = rules + (size_t)(r0 + rr) * Dn;
        uint32_t ix[4];
#pragma unroll
        for (int g = 0; g < 4; g++)
            ix[g] = ((uint32_t)rp[4*g]   & 3u)
                  | (((uint32_t)rp[4*g+1] & 3u) << 2)
                  | (((uint32_t)rp[4*g+2] & 3u) << 4)
                  | (((uint32_t)rp[4*g+3] & 3u) << 6);
        uint4 o;
        o.x = ( ix[0]        ) * 128u;
        o.y = ( 256u + ix[1] ) * 128u;
        o.z = ( 512u + ix[2] ) * 128u;
        o.w = ( 768u + ix[3] ) * 128u;
        g_offp[r0 + rr] = o;
    }
}

// ---------------------------------------------------------------------------
// main: ONE 1024-thread CTA per 32-row batch tile, all 2048 rules (CTA-local
// normalization). 32 warps/SM, 1 CTA/SM, grid 128.
// ---------------------------------------------------------------------------
// smem floats: tbl 1024*32 = 32768 | stage 32*16*34 = 17408 (overlays mf 2048
//              + pair 4096 during build) | xs 512 | red 12*32 = 384 | inv 32
#define STAGE_FLOATS (WARPS * CHUNK * SSTRIDE)
#define SMEM_FLOATS  (32768 + STAGE_FLOATS + 512 + 384 + 32)
#define SMEM_BYTES   (SMEM_FLOATS * 4)

__global__ void __launch_bounds__(THREADS, 1)
anfis_main(const float* __restrict__ x,
           const float* __restrict__ centers,
           const float* __restrict__ widths,
           float* __restrict__ out,     // (B, C)
           float* __restrict__ nf,      // (B, R)
           float* __restrict__ xext,    // (B, D+1)
           int write_aux) {
    extern __shared__ float sm[];
    float* tbl   = sm;                      // 1024*32
    float* stage = tbl + 32768;             // 32*16*34
    float* xs    = stage + STAGE_FLOATS;    // 32*16
    float* red   = xs + 512;                // 12*32
    float* inv_s = red + 384;               // 32
    float* mf    = stage;                   // overlay (build only) 64*32
    float* pair  = stage + 2048;            // overlay (build only) 128*32

    const int tid  = threadIdx.x;
    const int w    = tid >> 5;
    const int lane = tid & 31;
    const int b0   = blockIdx.x * BT;

    // ---- build phase ----
    for (int i = tid; i < BT * Dn; i += THREADS)
        xs[i] = x[(size_t)b0 * Dn + i];
    if (tid < 384) red[tid] = 0.f;
    __syncthreads();

    for (int e = tid; e < 64 * 32; e += THREADS) {
        int dm = e >> 5, b = e & 31;
        int d = dm >> 2, m = dm & 3;
        float cc = centers[d * Mn + m];
        float ww = widths[d * Mn + m];
        float df = xs[b * Dn + d] - cc;
        mf[dm * 32 + b] = expf(-df * df / (2.f * ww * ww));
    }
    __syncthreads();

    // pair tables: pair[p][i2][b], p = dim-pair 0..7
    for (int pp = w; pp < 128; pp += WARPS) {
        int pr = pp >> 4, i2 = pp & 15;
        pair[pp * 32 + lane] =
            mf[((2 * pr)     * 4 + (i2 & 3))  * 32 + lane] *
            mf[((2 * pr + 1) * 4 + (i2 >> 2)) * 32 + lane];
    }
    __syncthreads();

    // 4-dim group tables: 4 groups x 256 entries
    for (int pp = w; pp < 1024; pp += WARPS) {
        int g = pp >> 8, idx = pp & 255;
        tbl[pp * 32 + lane] =
            pair[((2 * g)     * 16 + (idx & 15)) * 32 + lane] *
            pair[((2 * g + 1) * 16 + (idx >> 4)) * 32 + lane];
    }
    __syncthreads();   // stage region free from here

    // ---- main loop: 64 rules/warp in chunks of 16 ----
    const char* tb = (const char*)tbl + lane * 4;
    const ulonglong2* cs2 = (const ulonglong2*)g_cs;
    const int rbase = w * RPW;
    float* stg = stage + w * (CHUNK * SSTRIDE);

    unsigned long long a01 = 0, a23 = 0, a45 = 0, a67 = 0, a89 = 0, aSF = 0;

    for (int ch = 0; ch < RPW / CHUNK; ch++) {
        const int r0 = rbase + ch * CHUNK;
#pragma unroll 4
        for (int rl = 0; rl < CHUNK; rl++) {
            const int r = r0 + rl;
            const uint4 o = g_offp[r];
            float f0 = *(const float*)(tb + o.x);
            float f1 = *(const float*)(tb + o.y);
            float f2 = *(const float*)(tb + o.z);
            float f3 = *(const float*)(tb + o.w);
            float f = (f0 * f1) * (f2 * f3);
            stg[rl * SSTRIDE + lane] = f;
            unsigned long long fp = bcast2(f);
            ulonglong2 v0 = cs2[r * 3 + 0];
            ulonglong2 v1 = cs2[r * 3 + 1];
            ulonglong2 v2 = cs2[r * 3 + 2];
            ffma2(a01, fp, v0.x); ffma2(a23, fp, v0.y);
            ffma2(a45, fp, v1.x); ffma2(a67, fp, v1.y);
            ffma2(a89, fp, v2.x); ffma2(aSF, fp, v2.y);  // .lo = fsum
        }
        __syncwarp();
        if (write_aux) {
            // transposed flush: raw f -> nf, coalesced 64B rows, bank-safe LDS
#pragma unroll
            for (int t2 = 0; t2 < 16; t2++) {
                int row = 2 * t2 + (lane >> 4);   // batch row 0..31
                int j = lane & 15;                // rule-in-chunk 0..15
                nf[(size_t)(b0 + row) * Rn + r0 + j] = stg[j * SSTRIDE + row];
            }
        }
        __syncwarp();
    }

    // ---- CTA reduction (smem atomics, one-time) ----
    {
        union { unsigned long long u; float2 f; } c0, c1, c2, c3, c4, c5;
        c0.u = a01; c1.u = a23; c2.u = a45; c3.u = a67; c4.u = a89; c5.u = aSF;
        atomicAdd(&red[ 0 * 32 + lane], c0.f.x);
        atomicAdd(&red[ 1 * 32 + lane], c0.f.y);
        atomicAdd(&red[ 2 * 32 + lane], c1.f.x);
        atomicAdd(&red[ 3 * 32 + lane], c1.f.y);
        atomicAdd(&red[ 4 * 32 + lane], c2.f.x);
        atomicAdd(&red[ 5 * 32 + lane], c2.f.y);
        atomicAdd(&red[ 6 * 32 + lane], c3.f.x);
        atomicAdd(&red[ 7 * 32 + lane], c3.f.y);
        atomicAdd(&red[ 8 * 32 + lane], c4.f.x);
        atomicAdd(&red[ 9 * 32 + lane], c4.f.y);
        atomicAdd(&red[10 * 32 + lane], c5.f.x);
    }
    __syncthreads();

    if (tid < 32)
        inv_s[tid] = 1.f / (red[10 * 32 + tid] + EPSV);
    __syncthreads();

    // out[b][c] = sx[b] * inv[b] * acc[b][c]
    if (tid < BT * Cn) {
        int b = tid & 31, c = tid >> 5;
        float s = 1.f;
#pragma unroll
        for (int d = 0; d < Dn; d++) s += xs[b * Dn + d];
        out[(size_t)(b0 + b) * Cn + c] = s * inv_s[b] * red[c * 32 + b];
    }

    if (write_aux) {
        if (tid < BT * (Dn + 1)) {   // 544 threads
            int b = tid / (Dn + 1), j = tid % (Dn + 1);
            xext[(size_t)(b0 + b) * (Dn + 1) + j] =
                (j < Dn) ? xs[b * Dn + j] : 1.f;
        }
        // in-place normalize of this CTA's nf region (L2-resident), float4
        __syncthreads();
        float4* p = (float4*)(nf + (size_t)b0 * Rn);
#pragma unroll
        for (int k = 0; k < 16; k++) {
            int i = tid + k * THREADS;          // 16384 float4 = 32 rows x 512
            float iv = inv_s[i >> 9];           // Rn/4 = 512 float4 per row
            float4 v = p[i];
            v.x *= iv; v.y *= iv; v.z *= iv; v.w *= iv;
            p[i] = v;
        }
    }
}

// ---------------------------------------------------------------------------
extern "C" void kernel_launch(void* const* d_in, const int* in_sizes, int n_in,
                              void* d_out, int out_size) {
    const float* x       = (const float*)d_in[0];
    const float* centers = (const float*)d_in[1];
    const float* widths  = (const float*)d_in[2];
    const float* cons    = (const float*)d_in[3];
    const int*   rules   = (const int*)d_in[4];

    float* out = (float*)d_out;
    const long total = (long)Bn * Cn + (long)Bn * Rn + (long)Bn * (Dn + 1);
    const int write_aux = (out_size >= total) ? 1 : 0;
    float* nf   = out + (size_t)Bn * Cn;
    float* xext = nf + (size_t)Bn * Rn;

    anfis_prep<<<Rn / 8, 256>>>(cons, rules);

    cudaFuncSetAttribute(anfis_main, cudaFuncAttributeMaxDynamicSharedMemorySize,
                         SMEM_BYTES);
    anfis_main<<<Bn / BT, THREADS, SMEM_BYTES>>>(x, centers, widths,
                                                 out, nf, xext, write_aux);
}

// round 9
// speedup vs baseline: 1.3184x; 1.1665x over previous
#include <cuda_runtime.h>
#include <stdint.h>

#define Bn 4096
#define Dn 16
#define Mn 4
#define Rn 2048
#define Cn 10
#define BT 32
#define WARPS 16
#define THREADS 512
#define RPW 128         // rules per warp
#define CHUNK 8
#define SSTRIDE 36      // (4j+row)%32 conflict-free both directions
#define EPSV 1e-9f

// scratch (module-load allocation, allowed)
__device__ uint4 g_offp[Rn];          // packed u16 table byte-offsets (5 per rule)
__device__ float g_cs[Rn * 12];       // folded consequents (+1.0 fsum slot, 0 pad)

__device__ __forceinline__ void ffma2(unsigned long long& acc,
                                      unsigned long long a,
                                      unsigned long long b) {
    asm("fma.rn.f32x2 %0, %1, %2, %0;" : "+l"(acc) : "l"(a), "l"(b));
}
__device__ __forceinline__ unsigned long long bcast2(float f) {
    unsigned long long r;
    asm("mov.b64 %0, {%1, %1};" : "=l"(r) : "f"(f));
    return r;
}

// ---------------------------------------------------------------------------
// prep: 8 rules per 256-thread CTA, smem-staged
// ---------------------------------------------------------------------------
__global__ void anfis_prep(const float* __restrict__ cons,
                           const int*   __restrict__ rules) {
    __shared__ float s[8 * 170];
    const int r0 = blockIdx.x * 8;
    const float* base = cons + (size_t)r0 * 170;
    for (int i = threadIdx.x; i < 8 * 170; i += 256) s[i] = base[i];
    __syncthreads();
    const int t = threadIdx.x;
    if (t < 80) {
        int rr = t / 10, c = t % 10;
        float a = 0.f;
#pragma unroll
        for (int j = 0; j < 17; j++) a += s[rr * 170 + j * 10 + c];
        g_cs[(size_t)(r0 + rr) * 12 + c] = a;
    } else if (t < 96) {
        int rr = (t - 80) >> 1;
        // slot [10] = 1.0 -> fsum rides the FFMA2 stream; [11] = 0
        g_cs[(size_t)(r0 + rr) * 12 + 10 + ((t - 80) & 1)] =
            ((t - 80) & 1) ? 0.f : 1.f;
    } else if (t < 104) {
        int rr = t - 96;
        const int* rp = rules + (size_t)(r0 + rr) * Dn;
        // groups: (0-2),(3-5),(6-8),(9-11) -> 64 entries; (12-15) -> 256
        uint32_t i0 = ((uint32_t)rp[0] & 3u) | (((uint32_t)rp[1] & 3u) << 2)
                    | (((uint32_t)rp[2] & 3u) << 4);
        uint32_t i1 = ((uint32_t)rp[3] & 3u) | (((uint32_t)rp[4] & 3u) << 2)
                    | (((uint32_t)rp[5] & 3u) << 4);
        uint32_t i2 = ((uint32_t)rp[6] & 3u) | (((uint32_t)rp[7] & 3u) << 2)
                    | (((uint32_t)rp[8] & 3u) << 4);
        uint32_t i3 = ((uint32_t)rp[9] & 3u) | (((uint32_t)rp[10] & 3u) << 2)
                    | (((uint32_t)rp[11] & 3u) << 4);
        uint32_t i4 = ((uint32_t)rp[12] & 3u) | (((uint32_t)rp[13] & 3u) << 2)
                    | (((uint32_t)rp[14] & 3u) << 4) | (((uint32_t)rp[15] & 3u) << 6);
        uint32_t o0 =            i0 * 128u;          // < 8192
        uint32_t o1 =  8192u  +  i1 * 128u;
        uint32_t o2 =  16384u +  i2 * 128u;
        uint32_t o3 =  24576u +  i3 * 128u;
        uint32_t o4 =  32768u +  i4 * 128u;          // <= 65408, fits u16
        uint4 o;
        o.x = o0 | (o1 << 16);
        o.y = o2 | (o3 << 16);
        o.z = o4;
        o.w = 0;
        g_offp[r0 + rr] = o;
    }
}

// ---------------------------------------------------------------------------
// main: one 512-thread CTA per 32-row batch tile, all 2048 rules.
// EVERYTHING in the rule loop is shared memory (lat-29), zero LDG.
// ---------------------------------------------------------------------------
// smem floats: tbl 512*32=16384 | stage 16*8*36=4608 (overlays mf 2048 +
//   pair 1024 at build) | csm 2048*12=24576 | soff 2048*4=8192 |
//   xs 512 | red 384 | inv 32   => 54688 floats = 213.6 KB
#define STAGE_FLOATS (WARPS * CHUNK * SSTRIDE)
#define SMEM_FLOATS  (16384 + STAGE_FLOATS + 24576 + 8192 + 512 + 384 + 32)
#define SMEM_BYTES   (SMEM_FLOATS * 4)

__global__ void __launch_bounds__(THREADS, 1)
anfis_main(const float* __restrict__ x,
           const float* __restrict__ centers,
           const float* __restrict__ widths,
           float* __restrict__ out,     // (B, C)
           float* __restrict__ nf,      // (B, R)
           float* __restrict__ xext,    // (B, D+1)
           int write_aux) {
    extern __shared__ float sm[];
    float* tbl   = sm;                      // 512*32
    float* stage = tbl + 16384;             // 16*8*36
    float* csm   = stage + STAGE_FLOATS;    // 2048*12
    uint4* soff  = (uint4*)(csm + 24576);   // 2048
    float* xs    = (float*)(soff + 2048);   // 32*16
    float* red   = xs + 512;                // 12*32
    float* inv_s = red + 384;               // 32
    float* mf    = stage;                   // overlay (build only) 64*32
    float* pair  = stage + 2048;            // overlay (build only) 32*32

    const int tid  = threadIdx.x;
    const int w    = tid >> 5;
    const int lane = tid & 31;
    const int b0   = blockIdx.x * BT;

    // ---- build phase ----
    for (int i = tid; i < BT * Dn; i += THREADS)
        xs[i] = x[(size_t)b0 * Dn + i];
    if (tid < 384) red[tid] = 0.f;

    // stage consequents + offsets into smem (coalesced, wide)
    {
        const float4* src = (const float4*)g_cs;
        float4* dst = (float4*)csm;
#pragma unroll
        for (int k = 0; k < 12; k++)
            dst[tid + k * THREADS] = src[tid + k * THREADS];   // 6144 float4
#pragma unroll
        for (int k = 0; k < 4; k++)
            soff[tid + k * THREADS] = g_offp[tid + k * THREADS];
    }
    __syncthreads();

    for (int e = tid; e < 64 * 32; e += THREADS) {
        int dm = e >> 5, b = e & 31;
        int d = dm >> 2, m = dm & 3;
        float cc = centers[d * Mn + m];
        float ww = widths[d * Mn + m];
        float df = xs[b * Dn + d] - cc;
        mf[dm * 32 + b] = expf(-df * df / (2.f * ww * ww));
    }
    __syncthreads();

    // groups 0-3: 3 dims each, 64 entries
    for (int pp = w; pp < 256; pp += WARPS) {
        int g = pp >> 6, idx = pp & 63;
        tbl[pp * 32 + lane] =
            mf[((3*g + 0) * 4 + ( idx       & 3)) * 32 + lane] *
            mf[((3*g + 1) * 4 + ((idx >> 2) & 3)) * 32 + lane] *
            mf[((3*g + 2) * 4 + ( idx >> 4     )) * 32 + lane];
    }
    // pair tables for group 4 (dims 12-13, 14-15)
    for (int pp = w; pp < 32; pp += WARPS) {
        int grp = pp >> 4, i2 = pp & 15;
        int d0 = 12 + grp * 2;
        pair[pp * 32 + lane] =
            mf[(d0     * 4 + (i2 & 3))  * 32 + lane] *
            mf[((d0+1) * 4 + (i2 >> 2)) * 32 + lane];
    }
    __syncthreads();
    // group 4: 4 dims, 256 entries
    for (int pp = w; pp < 256; pp += WARPS) {
        tbl[(256 + pp) * 32 + lane] =
            pair[(pp & 15) * 32 + lane] * pair[(16 + (pp >> 4)) * 32 + lane];
    }
    __syncthreads();   // stage region free from here

    // ---- main loop: 128 rules/warp in chunks of 8, all-smem ----
    const char* tb = (const char*)tbl + lane * 4;
    const ulonglong2* cs2 = (const ulonglong2*)csm;
    const int rbase = w * RPW;
    float* stg = stage + w * (CHUNK * SSTRIDE);

    unsigned long long a01 = 0, a23 = 0, a45 = 0, a67 = 0, a89 = 0, aSF = 0;

    for (int ch = 0; ch < RPW / CHUNK; ch++) {
        const int r0 = rbase + ch * CHUNK;
#pragma unroll
        for (int rl = 0; rl < CHUNK; rl++) {
            const int r = r0 + rl;
            const uint4 o = soff[r];                       // LDS.128 broadcast
            float f0 = *(const float*)(tb + (o.x & 0xFFFFu));
            float f1 = *(const float*)(tb + (o.x >> 16));
            float f2 = *(const float*)(tb + (o.y & 0xFFFFu));
            float f3 = *(const float*)(tb + (o.y >> 16));
            float f4 = *(const float*)(tb + o.z);
            float f = ((f0 * f1) * (f2 * f3)) * f4;
            stg[rl * SSTRIDE + lane] = f;
            unsigned long long fp = bcast2(f);
            ulonglong2 v0 = cs2[r * 3 + 0];                // LDS.128 broadcast
            ulonglong2 v1 = cs2[r * 3 + 1];
            ulonglong2 v2 = cs2[r * 3 + 2];
            ffma2(a01, fp, v0.x); ffma2(a23, fp, v0.y);
            ffma2(a45, fp, v1.x); ffma2(a67, fp, v1.y);
            ffma2(a89, fp, v2.x); ffma2(aSF, fp, v2.y);    // .lo = fsum
        }
        __syncwarp();
        if (write_aux) {
            // transposed flush: 4 rows x 8 rules per iteration
#pragma unroll
            for (int t2 = 0; t2 < 8; t2++) {
                int row = 4 * t2 + (lane >> 3);   // batch row
                int j = lane & 7;                 // rule-in-chunk
                nf[(size_t)(b0 + row) * Rn + r0 + j] = stg[j * SSTRIDE + row];
            }
        }
        __syncwarp();
    }

    // ---- CTA reduction (smem atomics, one-time) ----
    {
        union { unsigned long long u; float2 f; } c0, c1, c2, c3, c4, c5;
        c0.u = a01; c1.u = a23; c2.u = a45; c3.u = a67; c4.u = a89; c5.u = aSF;
        atomicAdd(&red[ 0 * 32 + lane], c0.f.x);
        atomicAdd(&red[ 1 * 32 + lane], c0.f.y);
        atomicAdd(&red[ 2 * 32 + lane], c1.f.x);
        atomicAdd(&red[ 3 * 32 + lane], c1.f.y);
        atomicAdd(&red[ 4 * 32 + lane], c2.f.x);
        atomicAdd(&red[ 5 * 32 + lane], c2.f.y);
        atomicAdd(&red[ 6 * 32 + lane], c3.f.x);
        atomicAdd(&red[ 7 * 32 + lane], c3.f.y);
        atomicAdd(&red[ 8 * 32 + lane], c4.f.x);
        atomicAdd(&red[ 9 * 32 + lane], c4.f.y);
        atomicAdd(&red[10 * 32 + lane], c5.f.x);
    }
    __syncthreads();

    if (tid < 32)
        inv_s[tid] = 1.f / (red[10 * 32 + tid] + EPSV);
    __syncthreads();

    // out[b][c] = sx[b] * inv[b] * acc[b][c]
    if (tid < BT * Cn) {
        int b = tid & 31, c = tid >> 5;
        float s = 1.f;
#pragma unroll
        for (int d = 0; d < Dn; d++) s += xs[b * Dn + d];
        out[(size_t)(b0 + b) * Cn + c] = s * inv_s[b] * red[c * 32 + b];
    }

    if (write_aux) {
        for (int i = tid; i < BT * (Dn + 1); i += THREADS) {
            int b = i / (Dn + 1), j = i % (Dn + 1);
            xext[(size_t)(b0 + b) * (Dn + 1) + j] =
                (j < Dn) ? xs[b * Dn + j] : 1.f;
        }
        // in-place normalize of this CTA's nf region (L2-resident), float4
        __syncthreads();
        float4* p = (float4*)(nf + (size_t)b0 * Rn);
#pragma unroll
        for (int k = 0; k < 32; k++) {
            int i = tid + k * THREADS;          // 16384 float4 = 32 rows x 512
            float iv = inv_s[i >> 9];           // Rn/4 = 512 float4 per row
            float4 v = p[i];
            v.x *= iv; v.y *= iv; v.z *= iv; v.w *= iv;
            p[i] = v;
        }
    }
}

// ---------------------------------------------------------------------------
extern "C" void kernel_launch(void* const* d_in, const int* in_sizes, int n_in,
                              void* d_out, int out_size) {
    const float* x       = (const float*)d_in[0];
    const float* centers = (const float*)d_in[1];
    const float* widths  = (const float*)d_in[2];
    const float* cons    = (const float*)d_in[3];
    const int*   rules   = (const int*)d_in[4];

    float* out = (float*)d_out;
    const long total = (long)Bn * Cn + (long)Bn * Rn + (long)Bn * (Dn + 1);
    const int write_aux = (out_size >= total) ? 1 : 0;
    float* nf   = out + (size_t)Bn * Cn;
    float* xext = nf + (size_t)Bn * Rn;

    anfis_prep<<<Rn / 8, 256>>>(cons, rules);

    cudaFuncSetAttribute(anfis_main, cudaFuncAttributeMaxDynamicSharedMemorySize,
                         SMEM_BYTES);
    anfis_main<<<Bn / BT, THREADS, SMEM_BYTES>>>(x, centers, widths,
                                                 out, nf, xext, write_aux);
}